// round 8
// baseline (speedup 1.0000x reference)
#include <cuda_runtime.h>

#define DV 160
#define HV 192
#define WV 160
#define VOL (DV * HV * WV)     // 4,915,200
#define SLICE (HV * WV)

// ---- Tile geometry: 32x16x10 voxels per block, halo 8 each side ----
#define TX 32
#define TY 16
#define TZ 10
#define HLO 8
#define EX (TX + 2 * HLO + 1)   // 49
#define EY (TY + 2 * HLO + 1)   // 33
#define EZ (TZ + 2 * HLO + 1)   // 27
#define SMEM_ELEMS (EX * EY * EZ)        // 43659
#define SMEM_BYTES (SMEM_ELEMS * 4)      // 174,636 B
#define NTHREADS 512

// Generic zero-padding trilinear for the 3-channel flow1 volume (rare path:
// stage-1 coords are effectively un-normalized twice -> >99.99% fully OOB).
__device__ __noinline__ void tri3_slow(const float* __restrict__ vol,
                                       float ix, float iy, float iz,
                                       float* __restrict__ o) {
    float x0f = floorf(ix), y0f = floorf(iy), z0f = floorf(iz);
    float tx = ix - x0f, ty = iy - y0f, tz = iz - z0f;
    int x0 = (int)x0f, y0 = (int)y0f, z0 = (int)z0f;
    float wx[2] = {1.f - tx, tx};
    float wy[2] = {1.f - ty, ty};
    float wz[2] = {1.f - tz, tz};
#pragma unroll
    for (int dz = 0; dz < 2; dz++) {
        int zc = z0 + dz;
        if (zc < 0 || zc >= DV) continue;
#pragma unroll
        for (int dy = 0; dy < 2; dy++) {
            int yc = y0 + dy;
            if (yc < 0 || yc >= HV) continue;
            int base = (zc * HV + yc) * WV;
            float wzy = wz[dz] * wy[dy];
#pragma unroll
            for (int dx = 0; dx < 2; dx++) {
                int xc = x0 + dx;
                if (xc < 0 || xc >= WV) continue;
                float wgt = wzy * wx[dx];
                int off = base + xc;
                o[0] = fmaf(__ldg(vol + off),           wgt, o[0]);
                o[1] = fmaf(__ldg(vol + VOL + off),     wgt, o[1]);
                o[2] = fmaf(__ldg(vol + 2 * VOL + off), wgt, o[2]);
            }
        }
    }
}

// Fully general global-memory src sample (zeros padding). Rare fallback for
// voxels whose stencil escapes the smem tile halo.
__device__ __noinline__ float tri1_global(const float* __restrict__ vol,
                                          int x0, int y0, int z0,
                                          float tx, float ty, float tz) {
    if (x0 <= -2 || x0 >= WV || y0 <= -2 || y0 >= HV || z0 <= -2 || z0 >= DV)
        return 0.f;
    float wx[2] = {1.f - tx, tx};
    float wy[2] = {1.f - ty, ty};
    float wz[2] = {1.f - tz, tz};
    float acc = 0.f;
#pragma unroll
    for (int dz = 0; dz < 2; dz++) {
        int zc = z0 + dz;
        if (zc < 0 || zc >= DV) continue;
#pragma unroll
        for (int dy = 0; dy < 2; dy++) {
            int yc = y0 + dy;
            if (yc < 0 || yc >= HV) continue;
            int base = (zc * HV + yc) * WV;
            float wzy = wz[dz] * wy[dy];
#pragma unroll
            for (int dx = 0; dx < 2; dx++) {
                int xc = x0 + dx;
                if (xc < 0 || xc >= WV) continue;
                acc = fmaf(__ldg(vol + base + xc), wzy * wx[dx], acc);
            }
        }
    }
    return acc;
}

// SMEM trilinear: all 8 corners guaranteed inside the tile (OOB-of-volume
// cells were stored as 0, matching zeros padding).
__device__ __forceinline__ float tri1_smem(const float* __restrict__ tile,
                                           int sx, int sy, int sz,
                                           float tx, float ty, float tz) {
    const float* p = tile + (sz * EY + sy) * EX + sx;
    const float* q = p + EY * EX;
    float v000 = p[0],  v001 = p[1];
    float v010 = p[EX], v011 = p[EX + 1];
    float v100 = q[0],  v101 = q[1];
    float v110 = q[EX], v111 = q[EX + 1];
    float c00 = fmaf(v001 - v000, tx, v000);
    float c01 = fmaf(v011 - v010, tx, v010);
    float c10 = fmaf(v101 - v100, tx, v100);
    float c11 = fmaf(v111 - v110, tx, v110);
    float c0  = fmaf(c01 - c00, ty, c00);
    float c1  = fmaf(c11 - c10, ty, c10);
    return fmaf(c1 - c0, tz, c0);
}

__global__ void __launch_bounds__(NTHREADS)
spatial_transformer_tiled(const float* __restrict__ src,
                          const float* __restrict__ flow1,
                          const float* __restrict__ flow2,
                          const float* __restrict__ rf_ptr,
                          float* __restrict__ out) {
    extern __shared__ float tile[];

    const int tx0 = blockIdx.x * TX;
    const int ty0 = blockIdx.y * TY;
    const int tz0 = blockIdx.z * TZ;
    const int sxlo = tx0 - HLO;
    const int sylo = ty0 - HLO;
    const int szlo = tz0 - HLO;

    // ---- Stage the src tile (+halo) into smem; volume-OOB cells -> 0. ----
    for (int e = threadIdx.x; e < SMEM_ELEMS; e += NTHREADS) {
        int ex = e % EX;
        int r  = e / EX;
        int ey = r % EY;
        int ez = r / EY;
        int gx = sxlo + ex, gy = sylo + ey, gz = szlo + ez;
        float v = 0.f;
        if ((unsigned)gx < WV && (unsigned)gy < HV && (unsigned)gz < DV)
            v = __ldg(src + (gz * HV + gy) * WV + gx);
        tile[e] = v;
    }
    __syncthreads();

    const int lx = threadIdx.x & (TX - 1);      // 0..31 (warp lanes span x)
    const int ly = threadIdx.x >> 5;            // 0..15
    const int w = tx0 + lx;
    const int h = ty0 + ly;
    const float wf = (float)w, hf = (float)h;

    const float rf = __ldg(rf_ptr);
    const float CD = (float)DV / (float)(DV - 1);
    const float CH = (float)HV / (float)(HV - 1);
    const float CW = (float)WV / (float)(WV - 1);

#pragma unroll 2
    for (int i = 0; i < TZ; i++) {
        const int d = tz0 + i;
        const float df = (float)d;
        const int idx = (d * HV + h) * WV + w;

        float f2z = __ldg(flow2 + idx);            // ch0 -> D axis
        float f2y = __ldg(flow2 + VOL + idx);      // ch1 -> H axis
        float f2x = __ldg(flow2 + 2 * VOL + idx);  // ch2 -> W axis

        // ---- Stage 1: flow1 warped by grid+flow2*rf (coords treated as
        // normalized -> almost always fully OOB -> zero). ----
        float gz1 = df + f2z * rf;
        float gy1 = hf + f2y * rf;
        float gx1 = wf + f2x * rf;
        float iz1 = fmaf(gz1, 80.f, 79.5f);   // ((g+1)*160-1)/2
        float iy1 = fmaf(gy1, 96.f, 95.5f);   // ((g+1)*192-1)/2
        float ix1 = fmaf(gx1, 80.f, 79.5f);

        float fw[3] = {0.f, 0.f, 0.f};
        if (ix1 >= -1.f && ix1 < (float)WV &&
            iy1 >= -1.f && iy1 < (float)HV &&
            iz1 >= -1.f && iz1 < (float)DV) {
            tri3_slow(flow1, ix1, iy1, iz1, fw);
        }
        float of0 = fw[0] + f2z;
        float of1 = fw[1] + f2y;
        float of2 = fw[2] + f2x;

        // ---- Stage 2: resample src at grid + out_flow*rf (renormalized). ----
        float nl0 = df + of0 * rf;
        float nl1 = hf + of1 * rf;
        float nl2 = wf + of2 * rf;
        float iz2 = fmaf(nl0, CD, -0.5f);
        float iy2 = fmaf(nl1, CH, -0.5f);
        float ix2 = fmaf(nl2, CW, -0.5f);

        float x0f = floorf(ix2), y0f = floorf(iy2), z0f = floorf(iz2);
        float tx = ix2 - x0f, ty = iy2 - y0f, tz = iz2 - z0f;
        int x0 = (int)x0f, y0 = (int)y0f, z0 = (int)z0f;
        int sx = x0 - sxlo, sy = y0 - sylo, sz = z0 - szlo;
        bool fast = (unsigned)sx <= (EX - 2) &&
                    (unsigned)sy <= (EY - 2) &&
                    (unsigned)sz <= (EZ - 2);

        float img;
        if (__all_sync(0xffffffffu, fast)) {
            img = tri1_smem(tile, sx, sy, sz, tx, ty, tz);
        } else {
            img = fast ? tri1_smem(tile, sx, sy, sz, tx, ty, tz)
                       : tri1_global(src, x0, y0, z0, tx, ty, tz);
        }

        // ---- Outputs: deform_2_img [V], then out_flow [3V]. ----
        out[idx]           = img;
        out[VOL + idx]     = of0;
        out[2 * VOL + idx] = of1;
        out[3 * VOL + idx] = of2;
    }
}

extern "C" void kernel_launch(void* const* d_in, const int* in_sizes, int n_in,
                              void* d_out, int out_size) {
    const float* src   = (const float*)d_in[0];
    const float* flow1 = (const float*)d_in[1];
    const float* flow2 = (const float*)d_in[2];
    // d_in[3] = meshgrid (recomputed in-kernel)
    const float* rf    = (const float*)d_in[4];
    float* out = (float*)d_out;

    static bool attr_set = false;
    if (!attr_set) {
        cudaFuncSetAttribute(spatial_transformer_tiled,
                             cudaFuncAttributeMaxDynamicSharedMemorySize,
                             SMEM_BYTES);
        attr_set = true;
    }

    dim3 grid(WV / TX, HV / TY, DV / TZ);   // 5 x 12 x 16 = 960 blocks
    spatial_transformer_tiled<<<grid, NTHREADS, SMEM_BYTES>>>(src, flow1, flow2,
                                                              rf, out);
}

// round 10
// speedup vs baseline: 2.2624x; 2.2624x over previous
#include <cuda_runtime.h>

#define DV 160
#define HV 192
#define WV 160
#define VOL (DV * HV * WV)     // 4,915,200

// ---- Tile geometry ----
#define TX 32
#define TY 16
#define TZ 8
#define HXL 8                   // x halo low (keeps rows float4-aligned)
#define HYL 5
#define HZL 6
#define EX 48                   // x extent: [tx0-8, tx0+40)  (hi margin 7 for x0+1)
#define EY 27                   // y extent: [ty0-5, ty0+22)
#define EZ 21                   // z extent: [tz0-6, tz0+15)
#define EXY (EX * EY)           // 1296
#define SMEM_ELEMS (EX * EY * EZ)    // 27216
#define SMEM_BYTES (SMEM_ELEMS * 4)  // 108,864 -> 2 blocks/SM
#define NTHREADS 512

// Generic zero-padding trilinear for the 3-channel flow1 volume (rare path:
// stage-1 coords are effectively un-normalized twice -> >99.99% fully OOB).
__device__ __noinline__ void tri3_slow(const float* __restrict__ vol,
                                       float ix, float iy, float iz,
                                       float* __restrict__ o) {
    float x0f = floorf(ix), y0f = floorf(iy), z0f = floorf(iz);
    float tx = ix - x0f, ty = iy - y0f, tz = iz - z0f;
    int x0 = (int)x0f, y0 = (int)y0f, z0 = (int)z0f;
    float wx[2] = {1.f - tx, tx};
    float wy[2] = {1.f - ty, ty};
    float wz[2] = {1.f - tz, tz};
#pragma unroll
    for (int dz = 0; dz < 2; dz++) {
        int zc = z0 + dz;
        if (zc < 0 || zc >= DV) continue;
#pragma unroll
        for (int dy = 0; dy < 2; dy++) {
            int yc = y0 + dy;
            if (yc < 0 || yc >= HV) continue;
            int base = (zc * HV + yc) * WV;
            float wzy = wz[dz] * wy[dy];
#pragma unroll
            for (int dx = 0; dx < 2; dx++) {
                int xc = x0 + dx;
                if (xc < 0 || xc >= WV) continue;
                float wgt = wzy * wx[dx];
                int off = base + xc;
                o[0] = fmaf(__ldg(vol + off),           wgt, o[0]);
                o[1] = fmaf(__ldg(vol + VOL + off),     wgt, o[1]);
                o[2] = fmaf(__ldg(vol + 2 * VOL + off), wgt, o[2]);
            }
        }
    }
}

// Fallback: global-memory src sample (zeros padding) for voxels whose stencil
// escapes the smem halo (~3% of voxels, few lanes per warp).
__device__ __noinline__ float tri1_global(const float* __restrict__ vol,
                                          int x0, int y0, int z0,
                                          float tx, float ty, float tz) {
    if (x0 <= -2 || x0 >= WV || y0 <= -2 || y0 >= HV || z0 <= -2 || z0 >= DV)
        return 0.f;
    float wx[2] = {1.f - tx, tx};
    float wy[2] = {1.f - ty, ty};
    float wz[2] = {1.f - tz, tz};
    float acc = 0.f;
#pragma unroll
    for (int dz = 0; dz < 2; dz++) {
        int zc = z0 + dz;
        if (zc < 0 || zc >= DV) continue;
#pragma unroll
        for (int dy = 0; dy < 2; dy++) {
            int yc = y0 + dy;
            if (yc < 0 || yc >= HV) continue;
            int base = (zc * HV + yc) * WV;
            float wzy = wz[dz] * wy[dy];
#pragma unroll
            for (int dx = 0; dx < 2; dx++) {
                int xc = x0 + dx;
                if (xc < 0 || xc >= WV) continue;
                acc = fmaf(__ldg(vol + base + xc), wzy * wx[dx], acc);
            }
        }
    }
    return acc;
}

__global__ void __launch_bounds__(NTHREADS, 2)
spatial_transformer_tiled(const float* __restrict__ src,
                          const float* __restrict__ flow1,
                          const float* __restrict__ flow2,
                          const float* __restrict__ rf_ptr,
                          float* __restrict__ out) {
    extern __shared__ float tile[];

    const int tx0 = blockIdx.x * TX;
    const int ty0 = blockIdx.y * TY;
    const int tz0 = blockIdx.z * TZ;
    const int sxlo = tx0 - HXL;
    const int sylo = ty0 - HYL;
    const int szlo = tz0 - HZL;

    // ---- Stage src tile (+halo) into smem with float4 rows.
    // Volume-OOB cells -> 0 (zeros padding becomes free in the fast path).
#pragma unroll 2
    for (int e4 = threadIdx.x; e4 < SMEM_ELEMS / 4; e4 += NTHREADS) {
        int ex4 = e4 % (EX / 4);          // 0..11
        int row = e4 / (EX / 4);
        int ey  = row % EY;
        int ez  = row / EY;
        int gx = sxlo + ex4 * 4;
        int gy = sylo + ey;
        int gz = szlo + ez;
        float4 v = make_float4(0.f, 0.f, 0.f, 0.f);
        if ((unsigned)gy < HV && (unsigned)gz < DV) {
            const float* p = src + (gz * HV + gy) * WV + gx;
            if (gx >= 0 && gx + 3 < WV) {
                v = __ldg((const float4*)p);          // aligned: gx % 4 == 0
            } else {
                if ((unsigned)(gx + 0) < WV) v.x = __ldg(p + 0);
                if ((unsigned)(gx + 1) < WV) v.y = __ldg(p + 1);
                if ((unsigned)(gx + 2) < WV) v.z = __ldg(p + 2);
                if ((unsigned)(gx + 3) < WV) v.w = __ldg(p + 3);
            }
        }
        ((float4*)tile)[e4] = v;
    }
    __syncthreads();

    const int lx = threadIdx.x & 31;      // warp lanes span x (coalesced I/O)
    const int ly = threadIdx.x >> 5;      // 0..15
    const int w = tx0 + lx;
    const int h = ty0 + ly;
    const float wf = (float)w, hf = (float)h;

    const float rf = __ldg(rf_ptr);
    const float CD = (float)DV / (float)(DV - 1);
    const float CH = (float)HV / (float)(HV - 1);
    const float CW = (float)WV / (float)(WV - 1);

#pragma unroll 2
    for (int i = 0; i < TZ; i++) {
        const int d = tz0 + i;
        const float df = (float)d;
        const int idx = (d * HV + h) * WV + w;

        float f2z = __ldg(flow2 + idx);            // ch0 -> D axis
        float f2y = __ldg(flow2 + VOL + idx);      // ch1 -> H axis
        float f2x = __ldg(flow2 + 2 * VOL + idx);  // ch2 -> W axis

        // ---- Stage 1: flow1 warped by grid+flow2*rf (coords treated as
        // normalized -> almost always fully OOB -> zero).
        float gz1 = df + f2z * rf;
        float gy1 = hf + f2y * rf;
        float gx1 = wf + f2x * rf;
        float iz1 = fmaf(gz1, 80.f, 79.5f);   // ((g+1)*160-1)/2
        float iy1 = fmaf(gy1, 96.f, 95.5f);   // ((g+1)*192-1)/2
        float ix1 = fmaf(gx1, 80.f, 79.5f);

        float fw[3] = {0.f, 0.f, 0.f};
        if (ix1 >= -1.f && ix1 < (float)WV &&
            iy1 >= -1.f && iy1 < (float)HV &&
            iz1 >= -1.f && iz1 < (float)DV) {
            tri3_slow(flow1, ix1, iy1, iz1, fw);
        }
        float of0 = fw[0] + f2z;
        float of1 = fw[1] + f2y;
        float of2 = fw[2] + f2x;

        // ---- Stage 2: resample src at grid + out_flow*rf (renormalized).
        float nl0 = df + of0 * rf;
        float nl1 = hf + of1 * rf;
        float nl2 = wf + of2 * rf;
        float iz2 = fmaf(nl0, CD, -0.5f);
        float iy2 = fmaf(nl1, CH, -0.5f);
        float ix2 = fmaf(nl2, CW, -0.5f);

        float x0f = floorf(ix2), y0f = floorf(iy2), z0f = floorf(iz2);
        float tx = ix2 - x0f, ty = iy2 - y0f, tz = iz2 - z0f;
        int x0 = (int)x0f, y0 = (int)y0f, z0 = (int)z0f;
        int sx = x0 - sxlo, sy = y0 - sylo, sz = z0 - szlo;

        float img;
        if ((unsigned)sx <= (EX - 2) &&
            (unsigned)sy <= (EY - 2) &&
            (unsigned)sz <= (EZ - 2)) {
            const float* p = tile + (sz * EY + sy) * EX + sx;
            const float* q = p + EXY;
            float v000 = p[0],  v001 = p[1];
            float v010 = p[EX], v011 = p[EX + 1];
            float v100 = q[0],  v101 = q[1];
            float v110 = q[EX], v111 = q[EX + 1];
            float c00 = fmaf(v001 - v000, tx, v000);
            float c01 = fmaf(v011 - v010, tx, v010);
            float c10 = fmaf(v101 - v100, tx, v100);
            float c11 = fmaf(v111 - v110, tx, v110);
            float c0  = fmaf(c01 - c00, ty, c00);
            float c1  = fmaf(c11 - c10, ty, c10);
            img = fmaf(c1 - c0, tz, c0);
        } else {
            img = tri1_global(src, x0, y0, z0, tx, ty, tz);
        }

        // ---- Outputs: deform_2_img [V], then out_flow [3V].
        out[idx]           = img;
        out[VOL + idx]     = of0;
        out[2 * VOL + idx] = of1;
        out[3 * VOL + idx] = of2;
    }
}

extern "C" void kernel_launch(void* const* d_in, const int* in_sizes, int n_in,
                              void* d_out, int out_size) {
    const float* src   = (const float*)d_in[0];
    const float* flow1 = (const float*)d_in[1];
    const float* flow2 = (const float*)d_in[2];
    // d_in[3] = meshgrid (recomputed in-kernel)
    const float* rf    = (const float*)d_in[4];
    float* out = (float*)d_out;

    // Unconditional (deterministic, capture-safe): opt in to >48KB dyn smem.
    cudaFuncSetAttribute(spatial_transformer_tiled,
                         cudaFuncAttributeMaxDynamicSharedMemorySize,
                         SMEM_BYTES);

    dim3 grid(WV / TX, HV / TY, DV / TZ);   // 5 x 12 x 20 = 1200 blocks
    spatial_transformer_tiled<<<grid, NTHREADS, SMEM_BYTES>>>(src, flow1, flow2,
                                                              rf, out);
}